// round 1
// baseline (speedup 1.0000x reference)
#include <cuda_runtime.h>

// ---------------------------------------------------------------------------
// Net_17188459119113: 4-bit quantized conv(1->16,3x3,VALID) + bias + relu +
// maxpool(4x4/4) + flatten + 4-bit quantized FC(576->10) + bias.
// B = 8192. x: [8192,1,28,28] f32. out: [8192,10] f32.
//
// Strategy: integer-code arithmetic (exact in fp32), scales applied at the end.
//   s = amax/7 + 1e-8 ; code = rint(clip(v/s, -7, 7)) ; value = code * s
// Kernels: K_init (zero amax accs, quantize weights) -> K_amax_x ->
//          K_conv (fused conv+bias+relu+pool, writes flat + flat-amax) -> K_fc.
// ---------------------------------------------------------------------------

#define BATCH     8192
#define IN_HW     28
#define IN_PIX    (IN_HW * IN_HW)        // 784
#define POOL_HW   6
#define FLAT_DIM  (16 * POOL_HW * POOL_HW)  // 576
#define CONV_W_N  (16 * 9)               // 144
#define FC_W_N    (10 * FLAT_DIM)        // 5760
#define CONV_THREADS_TOTAL (BATCH * POOL_HW * POOL_HW)  // 294912

// Scratch (device globals only — no runtime allocation allowed)
__device__ float        g_flat[BATCH * FLAT_DIM];   // post-pool activations (fp32)
__device__ unsigned int g_amax_x_bits;              // amax(|x|) as float bits
__device__ unsigned int g_amax_f_bits;              // amax(flat) as float bits
__device__ float        g_convw_q[CONV_W_N];        // conv weight integer codes (as float)
__device__ float        g_fcw_q[FC_W_N];            // fc weight integer codes (as float)
__device__ float        g_sw_conv;                  // conv weight scale
__device__ float        g_sw_fc;                    // fc weight scale

// ---------------------------------------------------------------------------
// K_init: reset amax accumulators (graph replays!), quantize both weight
// tensors. Single block.
// ---------------------------------------------------------------------------
__global__ void k_init(const float* __restrict__ conv_w,
                       const float* __restrict__ fc_w) {
    __shared__ unsigned int sm_cw, sm_fw;
    if (threadIdx.x == 0) {
        sm_cw = 0u; sm_fw = 0u;
        g_amax_x_bits = 0u;
        g_amax_f_bits = 0u;
    }
    __syncthreads();

    unsigned int m = 0u;
    for (int i = threadIdx.x; i < CONV_W_N; i += blockDim.x)
        m = max(m, __float_as_uint(fabsf(conv_w[i])));
    atomicMax(&sm_cw, m);
    m = 0u;
    for (int i = threadIdx.x; i < FC_W_N; i += blockDim.x)
        m = max(m, __float_as_uint(fabsf(fc_w[i])));
    atomicMax(&sm_fw, m);
    __syncthreads();

    float s_cw = __uint_as_float(sm_cw) / 7.0f + 1e-8f;
    float s_fw = __uint_as_float(sm_fw) / 7.0f + 1e-8f;
    if (threadIdx.x == 0) { g_sw_conv = s_cw; g_sw_fc = s_fw; }

    float inv_cw = 1.0f / s_cw;
    float inv_fw = 1.0f / s_fw;
    for (int i = threadIdx.x; i < CONV_W_N; i += blockDim.x)
        g_convw_q[i] = rintf(fminf(fmaxf(conv_w[i] * inv_cw, -7.0f), 7.0f));
    for (int i = threadIdx.x; i < FC_W_N; i += blockDim.x)
        g_fcw_q[i] = rintf(fminf(fmaxf(fc_w[i] * inv_fw, -7.0f), 7.0f));
}

// ---------------------------------------------------------------------------
// K_amax_x: global abs-max of x via float-bit atomicMax (|x| >= 0 so the bit
// pattern is order-isomorphic to the value). float4 loads, grid-stride.
// ---------------------------------------------------------------------------
__global__ void k_amax_x(const float4* __restrict__ x4, int n4) {
    unsigned int m = 0u;
    for (int i = blockIdx.x * blockDim.x + threadIdx.x; i < n4;
         i += gridDim.x * blockDim.x) {
        float4 v = x4[i];
        m = max(m, __float_as_uint(fabsf(v.x)));
        m = max(m, __float_as_uint(fabsf(v.y)));
        m = max(m, __float_as_uint(fabsf(v.z)));
        m = max(m, __float_as_uint(fabsf(v.w)));
    }
    #pragma unroll
    for (int off = 16; off > 0; off >>= 1)
        m = max(m, __shfl_xor_sync(0xFFFFFFFFu, m, off));
    __shared__ unsigned int sm;
    if (threadIdx.x == 0) sm = 0u;
    __syncthreads();
    if ((threadIdx.x & 31) == 0) atomicMax(&sm, m);
    __syncthreads();
    if (threadIdx.x == 0) atomicMax(&g_amax_x_bits, sm);
}

// ---------------------------------------------------------------------------
// K_conv: one thread per (b, ph, pw) pooled position, all 16 channels.
// Loads the 6x6 input patch once, quantizes to integer codes in registers,
// computes the 16 conv positions per channel (non-overlapping 4x4 pool
// window -> each conv output computed exactly once), max-pools, applies
// scale + bias + relu, writes flat, and contributes to amax(flat).
// ---------------------------------------------------------------------------
__global__ void __launch_bounds__(256)
k_conv(const float* __restrict__ x, const float* __restrict__ conv_b) {
    __shared__ float sw[CONV_W_N];
    __shared__ float sb[16];
    __shared__ unsigned int smax;
    if (threadIdx.x < CONV_W_N) sw[threadIdx.x] = g_convw_q[threadIdx.x];
    if (threadIdx.x < 16)       sb[threadIdx.x] = conv_b[threadIdx.x];
    if (threadIdx.x == 0)       smax = 0u;
    __syncthreads();

    int idx = blockIdx.x * blockDim.x + threadIdx.x;
    unsigned int lmax = 0u;
    if (idx < CONV_THREADS_TOTAL) {
        int pw = idx % 6;
        int t  = idx / 6;
        int ph = t % 6;
        int b  = t / 6;

        float s_x   = __uint_as_float(g_amax_x_bits) / 7.0f + 1e-8f;
        float inv_s = 1.0f / s_x;
        float sprod = s_x * g_sw_conv;

        const float* xp = x + b * IN_PIX + (4 * ph) * IN_HW + 4 * pw;

        // 6x6 quantized input patch (integer codes) in registers
        float p[36];
        #pragma unroll
        for (int r = 0; r < 6; r++) {
            #pragma unroll
            for (int c = 0; c < 6; c++) {
                float v = xp[r * IN_HW + c];
                p[r * 6 + c] =
                    rintf(fminf(fmaxf(v * inv_s, -7.0f), 7.0f));
            }
        }

        float* fout = g_flat + b * FLAT_DIM + ph * 6 + pw;

        #pragma unroll 1   // keep body in I-cache; 16 iterations
        for (int c = 0; c < 16; c++) {
            float w[9];
            #pragma unroll
            for (int k = 0; k < 9; k++) w[k] = sw[c * 9 + k];

            float mx = -3.0e38f;
            #pragma unroll
            for (int i = 0; i < 4; i++) {
                #pragma unroll
                for (int j = 0; j < 4; j++) {
                    float acc = 0.0f;
                    #pragma unroll
                    for (int kh = 0; kh < 3; kh++) {
                        #pragma unroll
                        for (int kw = 0; kw < 3; kw++) {
                            acc = fmaf(p[(i + kh) * 6 + (j + kw)],
                                       w[kh * 3 + kw], acc);
                        }
                    }
                    mx = fmaxf(mx, acc);
                }
            }
            // relu(max_pos * s_x*s_w + bias); relu/maxpool commute (monotone)
            float y = fmaxf(fmaf(mx, sprod, sb[c]), 0.0f);
            fout[c * 36] = y;
            lmax = max(lmax, __float_as_uint(y));   // y >= 0: bits monotone
        }
    }

    // block-level amax(flat) reduction, one global atomic per block
    #pragma unroll
    for (int off = 16; off > 0; off >>= 1)
        lmax = max(lmax, __shfl_xor_sync(0xFFFFFFFFu, lmax, off));
    if ((threadIdx.x & 31) == 0) atomicMax(&smax, lmax);
    __syncthreads();
    if (threadIdx.x == 0) atomicMax(&g_amax_f_bits, smax);
}

// ---------------------------------------------------------------------------
// K_fc: warp per batch row. Lanes stride over K=576, quantize flat on the
// fly to integer codes, FMA into 10 fp32 accumulators (exact integer math),
// warp-reduce, scale + bias, write out.
// ---------------------------------------------------------------------------
__global__ void __launch_bounds__(256)
k_fc(const float* __restrict__ fc_b, float* __restrict__ out) {
    __shared__ float swq[FC_W_N];   // 23 KB
    __shared__ float sbias[10];
    for (int i = threadIdx.x; i < FC_W_N; i += blockDim.x)
        swq[i] = g_fcw_q[i];
    if (threadIdx.x < 10) sbias[threadIdx.x] = fc_b[threadIdx.x];
    __syncthreads();

    int warp = threadIdx.x >> 5;
    int lane = threadIdx.x & 31;
    int b = blockIdx.x * 8 + warp;
    if (b >= BATCH) return;

    float s_f   = __uint_as_float(g_amax_f_bits) / 7.0f + 1e-8f;
    float inv_s = 1.0f / s_f;
    float sprod = s_f * g_sw_fc;

    const float* fr = g_flat + b * FLAT_DIM;

    float acc[10];
    #pragma unroll
    for (int o = 0; o < 10; o++) acc[o] = 0.0f;

    for (int k = lane; k < FLAT_DIM; k += 32) {
        float v = fr[k];                          // v >= 0 (post-relu)
        float q = rintf(fminf(v * inv_s, 7.0f));  // integer code
        #pragma unroll
        for (int o = 0; o < 10; o++)
            acc[o] = fmaf(q, swq[o * FLAT_DIM + k], acc[o]);
    }

    #pragma unroll
    for (int o = 0; o < 10; o++) {
        #pragma unroll
        for (int off = 16; off > 0; off >>= 1)
            acc[o] += __shfl_xor_sync(0xFFFFFFFFu, acc[o], off);
    }

    if (lane == 0) {
        #pragma unroll
        for (int o = 0; o < 10; o++)
            out[b * 10 + o] = fmaf(acc[o], sprod, sbias[o]);
    }
}

// ---------------------------------------------------------------------------
// kernel_launch — graph-capturable: plain launches on the default stream.
// Inputs (metadata order): x[6422528], conv_w[144], conv_b[16],
//                          fc_w[5760], fc_b[10]. Output: [81920] f32.
// ---------------------------------------------------------------------------
extern "C" void kernel_launch(void* const* d_in, const int* in_sizes, int n_in,
                              void* d_out, int out_size) {
    const float* x      = (const float*)d_in[0];
    const float* conv_w = (const float*)d_in[1];
    const float* conv_b = (const float*)d_in[2];
    const float* fc_w   = (const float*)d_in[3];
    const float* fc_b   = (const float*)d_in[4];
    float* out = (float*)d_out;

    k_init<<<1, 256>>>(conv_w, fc_w);

    int n4 = (BATCH * IN_PIX) / 4;  // 1605632, x is 16B-aligned harness alloc
    k_amax_x<<<1184, 256>>>((const float4*)x, n4);

    k_conv<<<(CONV_THREADS_TOTAL + 255) / 256, 256>>>(x, conv_b);

    k_fc<<<BATCH / 8, 256>>>(fc_b, out);
}

// round 2
// speedup vs baseline: 1.6087x; 1.6087x over previous
#include <cuda_runtime.h>

// ---------------------------------------------------------------------------
// Net_17188459119113: 4-bit quantized conv(1->16,3x3,VALID) + bias + relu +
// maxpool(4x4/4) + flatten + 4-bit quantized FC(576->10) + bias.
// B = 8192. x: [8192,1,28,28] f32. out: [8192,10] f32.
//
// R2: integer-code arithmetic via dp4a (exact s8 MACs), packed weights,
// funnel-shift sliding windows, float4 loads, redux.sync reductions.
// ---------------------------------------------------------------------------

#define BATCH     8192
#define IN_HW     28
#define IN_PIX    (IN_HW * IN_HW)           // 784
#define FLAT_DIM  576
#define FC_GROUPS 144                        // 576 / 4
#define CONV_THREADS_TOTAL (BATCH * 36)      // 294912

// Scratch (device globals only)
__device__ float        g_flat[BATCH * FLAT_DIM];
__device__ unsigned int g_amax_x_bits;
__device__ unsigned int g_amax_f_bits;
__device__ int          g_convw_pack[16 * 3];    // per channel: 3 rows, bytes [w0,w1,w2,0]
__device__ int          g_fcw_pack[10 * FC_GROUPS];
__device__ float        g_sw_conv;
__device__ float        g_sw_fc;

__device__ __forceinline__ int qcode(float v, float inv_s) {
    return __float2int_rn(fminf(fmaxf(v * inv_s, -7.0f), 7.0f));
}
__device__ __forceinline__ unsigned pack4(int a, int b, int c, int d) {
    return (unsigned)((a & 0xff) | ((b & 0xff) << 8) | ((c & 0xff) << 16) | (d << 24));
}

// ---------------------------------------------------------------------------
// K_init: reset amax accumulators, quantize + byte-pack both weight tensors.
// ---------------------------------------------------------------------------
__global__ void k_init(const float* __restrict__ conv_w,
                       const float* __restrict__ fc_w) {
    __shared__ unsigned int sm_cw, sm_fw;
    if (threadIdx.x == 0) {
        sm_cw = 0u; sm_fw = 0u;
        g_amax_x_bits = 0u;
        g_amax_f_bits = 0u;
    }
    __syncthreads();

    unsigned int m = 0u;
    for (int i = threadIdx.x; i < 144; i += blockDim.x)
        m = max(m, __float_as_uint(fabsf(conv_w[i])));
    m = __reduce_max_sync(0xFFFFFFFFu, m);
    if ((threadIdx.x & 31) == 0) atomicMax(&sm_cw, m);
    m = 0u;
    for (int i = threadIdx.x; i < 10 * FLAT_DIM; i += blockDim.x)
        m = max(m, __float_as_uint(fabsf(fc_w[i])));
    m = __reduce_max_sync(0xFFFFFFFFu, m);
    if ((threadIdx.x & 31) == 0) atomicMax(&sm_fw, m);
    __syncthreads();

    float s_cw = __uint_as_float(sm_cw) / 7.0f + 1e-8f;
    float s_fw = __uint_as_float(sm_fw) / 7.0f + 1e-8f;
    if (threadIdx.x == 0) { g_sw_conv = s_cw; g_sw_fc = s_fw; }

    float inv_cw = 1.0f / s_cw;
    float inv_fw = 1.0f / s_fw;

    // conv weights: [16][3][3] -> 48 packed ints, byte3 = 0
    for (int i = threadIdx.x; i < 48; i += blockDim.x) {
        const float* wr = conv_w + i * 3;   // i = c*3 + row
        g_convw_pack[i] = (int)pack4(qcode(wr[0], inv_cw),
                                     qcode(wr[1], inv_cw),
                                     qcode(wr[2], inv_cw), 0);
    }
    // fc weights: [10][576] -> [10][144] packed
    for (int i = threadIdx.x; i < 10 * FC_GROUPS; i += blockDim.x) {
        int o = i / FC_GROUPS, g = i % FC_GROUPS;
        const float* wr = fc_w + o * FLAT_DIM + g * 4;
        g_fcw_pack[i] = (int)pack4(qcode(wr[0], inv_fw), qcode(wr[1], inv_fw),
                                   qcode(wr[2], inv_fw), qcode(wr[3], inv_fw));
    }
}

// ---------------------------------------------------------------------------
// K_amax_x: global abs-max of x (float-bit max; |x| bits are order-isomorphic)
// ---------------------------------------------------------------------------
__global__ void k_amax_x(const float4* __restrict__ x4, int n4) {
    unsigned int m = 0u;
    for (int i = blockIdx.x * blockDim.x + threadIdx.x; i < n4;
         i += gridDim.x * blockDim.x) {
        float4 v = x4[i];
        m = max(m, __float_as_uint(fabsf(v.x)));
        m = max(m, __float_as_uint(fabsf(v.y)));
        m = max(m, __float_as_uint(fabsf(v.z)));
        m = max(m, __float_as_uint(fabsf(v.w)));
    }
    m = __reduce_max_sync(0xFFFFFFFFu, m);
    __shared__ unsigned int sm;
    if (threadIdx.x == 0) sm = 0u;
    __syncthreads();
    if ((threadIdx.x & 31) == 0) atomicMax(&sm, m);
    __syncthreads();
    if (threadIdx.x == 0) atomicMax(&g_amax_f_bits == 0 ? &g_amax_x_bits : &g_amax_x_bits, sm); // plain target below
}

// (clean version of the final atomic, avoiding the ternary above)
__global__ void k_amax_x2(const float4* __restrict__ x4, int n4) {
    unsigned int m = 0u;
    for (int i = blockIdx.x * blockDim.x + threadIdx.x; i < n4;
         i += gridDim.x * blockDim.x) {
        float4 v = x4[i];
        m = max(m, __float_as_uint(fabsf(v.x)));
        m = max(m, __float_as_uint(fabsf(v.y)));
        m = max(m, __float_as_uint(fabsf(v.z)));
        m = max(m, __float_as_uint(fabsf(v.w)));
    }
    m = __reduce_max_sync(0xFFFFFFFFu, m);
    __shared__ unsigned int sm;
    if (threadIdx.x == 0) sm = 0u;
    __syncthreads();
    if ((threadIdx.x & 31) == 0) atomicMax(&sm, m);
    __syncthreads();
    if (threadIdx.x == 0) atomicMax(&g_amax_x_bits, sm);
}

// ---------------------------------------------------------------------------
// K_conv: thread per (b, ph, pw). Quantize 6x6 patch to int codes, pack rows
// into bytes, build 24 sliding windows (funnel shift), then per channel:
// 16 positions x 3 dp4a, int max-pool, scale+bias+relu, write flat + amax.
// ---------------------------------------------------------------------------
__global__ void __launch_bounds__(256)
k_conv(const float* __restrict__ x, const float* __restrict__ conv_b) {
    __shared__ int   swp[48];
    __shared__ float sb[16];
    __shared__ unsigned int smax;
    if (threadIdx.x < 48) swp[threadIdx.x] = g_convw_pack[threadIdx.x];
    if (threadIdx.x < 16) sb[threadIdx.x]  = conv_b[threadIdx.x];
    if (threadIdx.x == 0) smax = 0u;
    __syncthreads();

    int idx = blockIdx.x * blockDim.x + threadIdx.x;
    unsigned int lmax = 0u;
    if (idx < CONV_THREADS_TOTAL) {
        int pw = idx % 6;
        int t  = idx / 6;
        int ph = t % 6;
        int b  = t / 6;

        float s_x   = __uint_as_float(g_amax_x_bits) / 7.0f + 1e-8f;
        float inv_s = 1.0f / s_x;
        float sprod = s_x * g_sw_conv;

        // xp is 16B-aligned: b*784 + 112*ph + 4*pw, all multiples of 4 floats
        const float* xp = x + b * IN_PIX + (4 * ph) * IN_HW + 4 * pw;

        unsigned win[24];   // [row 0..5][window 0..3]
        #pragma unroll
        for (int r = 0; r < 6; r++) {
            float4 v4 = *(const float4*)(xp + r * IN_HW);
            float2 v2 = *(const float2*)(xp + r * IN_HW + 4);
            int i0 = qcode(v4.x, inv_s), i1 = qcode(v4.y, inv_s);
            int i2 = qcode(v4.z, inv_s), i3 = qcode(v4.w, inv_s);
            int i4 = qcode(v2.x, inv_s), i5 = qcode(v2.y, inv_s);
            unsigned p0 = pack4(i0, i1, i2, i3);
            unsigned p1 = (unsigned)((i4 & 0xff) | ((i5 & 0xff) << 8));
            win[r * 4 + 0] = p0;
            win[r * 4 + 1] = __funnelshift_r(p0, p1, 8);
            win[r * 4 + 2] = __funnelshift_r(p0, p1, 16);
            win[r * 4 + 3] = __funnelshift_r(p0, p1, 24);
        }

        float* fout = g_flat + b * FLAT_DIM + ph * 6 + pw;

        #pragma unroll 1   // 16 channel iterations; keep body in I-cache
        for (int c = 0; c < 16; c++) {
            int w0 = swp[c * 3 + 0];
            int w1 = swp[c * 3 + 1];
            int w2 = swp[c * 3 + 2];

            int mx = -(1 << 30);
            #pragma unroll
            for (int i = 0; i < 4; i++) {
                #pragma unroll
                for (int j = 0; j < 4; j++) {
                    int acc = __dp4a((int)win[i * 4 + j],       w0, 0);
                    acc     = __dp4a((int)win[(i + 1) * 4 + j], w1, acc);
                    acc     = __dp4a((int)win[(i + 2) * 4 + j], w2, acc);
                    mx = max(mx, acc);
                }
            }
            float y = fmaxf(fmaf((float)mx, sprod, sb[c]), 0.0f);
            fout[c * 36] = y;
            lmax = max(lmax, __float_as_uint(y));   // y >= 0
        }
    }

    lmax = __reduce_max_sync(0xFFFFFFFFu, lmax);
    if ((threadIdx.x & 31) == 0) atomicMax(&smax, lmax);
    __syncthreads();
    if (threadIdx.x == 0) atomicMax(&g_amax_f_bits, smax);
}

// ---------------------------------------------------------------------------
// K_fc: warp per batch row. float4 load + quantize + byte-pack 4 codes,
// 10 dp4a per group, redux.sync add, lanes 0..9 write the 10 outputs.
// ---------------------------------------------------------------------------
__global__ void __launch_bounds__(256)
k_fc(const float* __restrict__ fc_b, float* __restrict__ out) {
    __shared__ int   swq[10 * FC_GROUPS];   // 5.6 KB
    __shared__ float sbias[10];
    for (int i = threadIdx.x; i < 10 * FC_GROUPS; i += blockDim.x)
        swq[i] = g_fcw_pack[i];
    if (threadIdx.x < 10) sbias[threadIdx.x] = fc_b[threadIdx.x];
    __syncthreads();

    int warp = threadIdx.x >> 5;
    int lane = threadIdx.x & 31;
    int b = blockIdx.x * 8 + warp;
    if (b >= BATCH) return;

    float s_f   = __uint_as_float(g_amax_f_bits) / 7.0f + 1e-8f;
    float inv_s = 1.0f / s_f;
    float sprod = s_f * g_sw_fc;

    const float4* fr4 = (const float4*)(g_flat + b * FLAT_DIM);  // 144 groups

    int acc[10];
    #pragma unroll
    for (int o = 0; o < 10; o++) acc[o] = 0;

    #pragma unroll
    for (int it = 0; it < 5; it++) {
        int g = lane + it * 32;
        if (g < FC_GROUPS) {
            float4 v = fr4[g];
            // v >= 0 (post-relu): clamp upper side only
            int i0 = __float2int_rn(fminf(v.x * inv_s, 7.0f));
            int i1 = __float2int_rn(fminf(v.y * inv_s, 7.0f));
            int i2 = __float2int_rn(fminf(v.z * inv_s, 7.0f));
            int i3 = __float2int_rn(fminf(v.w * inv_s, 7.0f));
            int p = (int)pack4(i0, i1, i2, i3);
            #pragma unroll
            for (int o = 0; o < 10; o++)
                acc[o] = __dp4a(p, swq[o * FC_GROUPS + g], acc[o]);
        }
    }

    #pragma unroll
    for (int o = 0; o < 10; o++)
        acc[o] = __reduce_add_sync(0xFFFFFFFFu, acc[o]);

    if (lane < 10)
        out[b * 10 + lane] = fmaf((float)acc[lane], sprod, sbias[lane]);
}

// ---------------------------------------------------------------------------
// kernel_launch — graph-capturable, default stream.
// ---------------------------------------------------------------------------
extern "C" void kernel_launch(void* const* d_in, const int* in_sizes, int n_in,
                              void* d_out, int out_size) {
    const float* x      = (const float*)d_in[0];
    const float* conv_w = (const float*)d_in[1];
    const float* conv_b = (const float*)d_in[2];
    const float* fc_w   = (const float*)d_in[3];
    const float* fc_b   = (const float*)d_in[4];
    float* out = (float*)d_out;

    k_init<<<1, 256>>>(conv_w, fc_w);

    int n4 = (BATCH * IN_PIX) / 4;
    k_amax_x2<<<1184, 256>>>((const float4*)x, n4);

    k_conv<<<(CONV_THREADS_TOTAL + 255) / 256, 256>>>(x, conv_b);

    k_fc<<<BATCH / 8, 256>>>(fc_b, out);
}